// round 10
// baseline (speedup 1.0000x reference)
#include <cuda_runtime.h>

#define D_MODEL 2048
#define SEQ_L   256
#define BATCH_N 128
#define CHUNK   128           // channels per block
#define B_SPLIT 64            // grid.y; each block handles batches {by, by+64}

struct cf { float re, im; };
__device__ __forceinline__ cf cmulf(cf a, cf b) {
    return { a.re*b.re - a.im*b.im, a.re*b.im + a.im*b.re };
}
__device__ __forceinline__ cf caddf(cf a, cf b) { return { a.re + b.re, a.im + b.im }; }
__device__ __forceinline__ cf cdivf(cf a, cf b) {
    float inv = 1.0f / (b.re*b.re + b.im*b.im);
    return { (a.re*b.re + a.im*b.im)*inv, (a.im*b.re - a.re*b.im)*inv };
}

// Single-wave persistent variant: 1024 blocks <= 148 SM x 8 resident (1184),
// so the whole grid is one wave -- no wave transition, no partial second wave.
// Each block: taps once (threads 0..127), then streams TWO batches.
__global__ __launch_bounds__(256, 8) void s4d_fused_kernel(
    const float* __restrict__ u,
    const float* __restrict__ A_real, const float* __restrict__ A_imag,
    const float* __restrict__ B_real, const float* __restrict__ B_imag,
    const float* __restrict__ C_real, const float* __restrict__ C_imag,
    const float* __restrict__ Dvec,
    float* __restrict__ out)
{
    __shared__ float s_g0[CHUNK];
    __shared__ float s_g1[CHUNK];

    const int tid    = threadIdx.x;
    const int chunk0 = blockIdx.x * CHUNK;

    if (tid < CHUNK) {
        const int d = chunk0 + tid;
        const float a0r = -expf(A_real[2*d]),   a0i = A_imag[2*d];
        const float a1r = -expf(A_real[2*d+1]), a1i = A_imag[2*d+1];

        cf p0 = cdivf({1.f + 0.5f*a0r,  0.5f*a0i},
                      {1.f - 0.5f*a0r, -0.5f*a0i});
        cf p1 = cdivf({1.f + 0.5f*a1r,  0.5f*a1i},
                      {1.f - 0.5f*a1r, -0.5f*a1i});

        cf m00 = p0, m01 = {-1.f, 0.f}, m11 = p1;
        #pragma unroll
        for (int s = 0; s < 8; s++) {           // M <- M^2 (symmetric), => M^256
            cf m01sq = cmulf(m01, m01);
            cf n00 = caddf(cmulf(m00, m00), m01sq);
            cf n01 = cmulf(m01, caddf(m00, m11));
            cf n11 = caddf(m01sq, cmulf(m11, m11));
            m00 = n00; m01 = n01; m11 = n11;
        }

        cf B0 = { B_real[2*d],   B_imag[2*d]   };
        cf B1 = { B_real[2*d+1], B_imag[2*d+1] };
        cf C0 = { C_real[2*d],   C_imag[2*d]   };
        cf C1 = { C_real[2*d+1], C_imag[2*d+1] };

        cf t0 = caddf(cmulf({1.f - m00.re, -m00.im}, B0),
                      cmulf({     -m01.re, -m01.im}, B1));
        cf t1 = caddf(cmulf({     -m01.re, -m01.im}, B0),
                      cmulf({1.f - m11.re, -m11.im}, B1));

        s_g0[tid] = (C0.re*t0.re - C0.im*t0.im) + Dvec[d];
        s_g1[tid] = (C1.re*t1.re - C1.im*t1.im);
    }
    __syncthreads();

    const int lane = tid & 31;          // float4 column within chunk
    const int w    = tid >> 5;          // t-group
    const int t0i  = w * 32;

    const float4 g0 = *reinterpret_cast<const float4*>(s_g0 + lane*4);
    const float4 g1 = *reinterpret_cast<const float4*>(s_g1 + lane*4);

    #pragma unroll 1
    for (int bi = 0; bi < 2; bi++) {
        const unsigned int b = (unsigned int)blockIdx.y + (unsigned int)bi * B_SPLIT;
        const unsigned int base =
            (b * SEQ_L + (unsigned int)t0i) * D_MODEL
            + (unsigned int)chunk0 + (unsigned int)lane * 4u;

        const float4* __restrict__ up = reinterpret_cast<const float4*>(u + base);
        float4*       __restrict__ op = reinterpret_cast<float4*>(out + base);

        float4 uprev;
        if (t0i == 0) uprev = make_float4(0.f, 0.f, 0.f, 0.f);
        else          uprev = *reinterpret_cast<const float4*>(u + base - D_MODEL);

        #pragma unroll 8
        for (int k = 0; k < 32; k++) {
            float4 uv = up[(unsigned int)k * (D_MODEL/4)];
            float4 o;
            o.x = fmaf(g0.x, uv.x, g1.x * uprev.x);
            o.y = fmaf(g0.y, uv.y, g1.y * uprev.y);
            o.z = fmaf(g0.z, uv.z, g1.z * uprev.z);
            o.w = fmaf(g0.w, uv.w, g1.w * uprev.w);
            op[(unsigned int)k * (D_MODEL/4)] = o;
            uprev = uv;
        }
    }
}

extern "C" void kernel_launch(void* const* d_in, const int* in_sizes, int n_in,
                              void* d_out, int out_size) {
    const float* u      = (const float*)d_in[0];
    const float* A_real = (const float*)d_in[1];
    const float* A_imag = (const float*)d_in[2];
    const float* B_real = (const float*)d_in[3];
    const float* B_imag = (const float*)d_in[4];
    const float* C_real = (const float*)d_in[5];
    const float* C_imag = (const float*)d_in[6];
    const float* Dvec   = (const float*)d_in[7];
    float* out = (float*)d_out;

    dim3 grid(D_MODEL / CHUNK, B_SPLIT);   // (16, 64) = 1024 blocks: one wave
    s4d_fused_kernel<<<grid, 256>>>(u, A_real, A_imag, B_real, B_imag,
                                    C_real, C_imag, Dvec, out);
}

// round 13
// speedup vs baseline: 1.1731x; 1.1731x over previous
#include <cuda_runtime.h>

#define D_MODEL 2048
#define SEQ_L   256
#define BATCH_N 128
#define CHUNK   128           // channels per block (best-measured shape across R4-R10)

struct cf { float re, im; };
__device__ __forceinline__ cf cmulf(cf a, cf b) {
    return { a.re*b.re - a.im*b.im, a.re*b.im + a.im*b.re };
}
__device__ __forceinline__ cf caddf(cf a, cf b) { return { a.re + b.re, a.im + b.im }; }
__device__ __forceinline__ cf cdivf(cf a, cf b) {
    float inv = 1.0f / (b.re*b.re + b.im*b.im);
    return { (a.re*b.re + a.im*b.im)*inv, (a.im*b.re - a.re*b.im)*inv };
}

// FINAL: exact R4 configuration — best measured (kernel 80.2us, DRAM 78.0%,
// regs 32, occ 86.8%). Exhaustively compared against: CHUNK=256 (-6.5us),
// __ldcs/__stcs (-2.5us, regalloc damage), time-split grid (-2.1us),
// single-wave persistent (-10.6us, lost block-level MLP). 512 MB traffic is
// the floor; ~6.2 TB/s is the sm_103a LTS ceiling for a 1:1 fp32 R/W stream.
//
// Phase 1 (threads 0..127): fp32 taps for this block's 128 channels -> smem.
//   dA = [[p0,-1],[-1,p1]] (off-diagonals exactly -1 from the reference's
//   elementwise division); 8 symmetric squarings => dA^256.
//   g0[d] = Re(C0*((1-P00)B0 - P01*B1)) + D[d];  g1[d] = Re(C1*(-P01*B0 + (1-P11)B1)).
// Phase 2 (all 256 threads): t-major 2-tap causal conv,
//   out[b,t,d] = g0[d]*u[b,t,d] + g1[d]*u[b,t-1,d]; u[t-1] register-carried.
__global__ __launch_bounds__(256) void s4d_fused_kernel(
    const float* __restrict__ u,
    const float* __restrict__ A_real, const float* __restrict__ A_imag,
    const float* __restrict__ B_real, const float* __restrict__ B_imag,
    const float* __restrict__ C_real, const float* __restrict__ C_imag,
    const float* __restrict__ Dvec,
    float* __restrict__ out)
{
    __shared__ float s_g0[CHUNK];
    __shared__ float s_g1[CHUNK];

    const int tid    = threadIdx.x;
    const int chunk0 = blockIdx.x * CHUNK;

    if (tid < CHUNK) {
        const int d = chunk0 + tid;
        const float a0r = -expf(A_real[2*d]),   a0i = A_imag[2*d];
        const float a1r = -expf(A_real[2*d+1]), a1i = A_imag[2*d+1];

        cf p0 = cdivf({1.f + 0.5f*a0r,  0.5f*a0i},
                      {1.f - 0.5f*a0r, -0.5f*a0i});
        cf p1 = cdivf({1.f + 0.5f*a1r,  0.5f*a1i},
                      {1.f - 0.5f*a1r, -0.5f*a1i});

        cf m00 = p0, m01 = {-1.f, 0.f}, m11 = p1;
        #pragma unroll
        for (int s = 0; s < 8; s++) {           // M <- M^2 (symmetric), => M^256
            cf m01sq = cmulf(m01, m01);
            cf n00 = caddf(cmulf(m00, m00), m01sq);
            cf n01 = cmulf(m01, caddf(m00, m11));
            cf n11 = caddf(m01sq, cmulf(m11, m11));
            m00 = n00; m01 = n01; m11 = n11;
        }

        cf B0 = { B_real[2*d],   B_imag[2*d]   };
        cf B1 = { B_real[2*d+1], B_imag[2*d+1] };
        cf C0 = { C_real[2*d],   C_imag[2*d]   };
        cf C1 = { C_real[2*d+1], C_imag[2*d+1] };

        cf t0 = caddf(cmulf({1.f - m00.re, -m00.im}, B0),
                      cmulf({     -m01.re, -m01.im}, B1));
        cf t1 = caddf(cmulf({     -m01.re, -m01.im}, B0),
                      cmulf({1.f - m11.re, -m11.im}, B1));

        s_g0[tid] = (C0.re*t0.re - C0.im*t0.im) + Dvec[d];
        s_g1[tid] = (C1.re*t1.re - C1.im*t1.im);
    }
    __syncthreads();

    const int lane = tid & 31;          // float4 column within chunk
    const int w    = tid >> 5;          // t-group
    const int t0i  = w * 32;

    const float4 g0 = *reinterpret_cast<const float4*>(s_g0 + lane*4);
    const float4 g1 = *reinterpret_cast<const float4*>(s_g1 + lane*4);

    const unsigned int base =
        ((unsigned int)blockIdx.y * SEQ_L + (unsigned int)t0i) * D_MODEL
        + (unsigned int)chunk0 + (unsigned int)lane * 4u;

    const float4* __restrict__ up = reinterpret_cast<const float4*>(u + base);
    float4*       __restrict__ op = reinterpret_cast<float4*>(out + base);

    float4 uprev;
    if (t0i == 0) uprev = make_float4(0.f, 0.f, 0.f, 0.f);
    else          uprev = *reinterpret_cast<const float4*>(u + base - D_MODEL);

    #pragma unroll 8
    for (int k = 0; k < 32; k++) {
        float4 uv = up[(unsigned int)k * (D_MODEL/4)];
        float4 o;
        o.x = fmaf(g0.x, uv.x, g1.x * uprev.x);
        o.y = fmaf(g0.y, uv.y, g1.y * uprev.y);
        o.z = fmaf(g0.z, uv.z, g1.z * uprev.z);
        o.w = fmaf(g0.w, uv.w, g1.w * uprev.w);
        op[(unsigned int)k * (D_MODEL/4)] = o;
        uprev = uv;
    }
}

extern "C" void kernel_launch(void* const* d_in, const int* in_sizes, int n_in,
                              void* d_out, int out_size) {
    const float* u      = (const float*)d_in[0];
    const float* A_real = (const float*)d_in[1];
    const float* A_imag = (const float*)d_in[2];
    const float* B_real = (const float*)d_in[3];
    const float* B_imag = (const float*)d_in[4];
    const float* C_real = (const float*)d_in[5];
    const float* C_imag = (const float*)d_in[6];
    const float* Dvec   = (const float*)d_in[7];
    float* out = (float*)d_out;

    dim3 grid(D_MODEL / CHUNK, BATCH_N);   // (16, 128) = 2048 blocks
    s4d_fused_kernel<<<grid, 256>>>(u, A_real, A_imag, B_real, B_imag,
                                    C_real, C_imag, Dvec, out);
}

// round 14
// speedup vs baseline: 1.2331x; 1.0512x over previous
#include <cuda_runtime.h>

#define D_MODEL 2048
#define SEQ_L   256
#define BATCH_N 128
#define CHUNK   128           // channels per block (best-median shape, R4)

struct cf { float re, im; };
__device__ __forceinline__ cf cmulf(cf a, cf b) {
    return { a.re*b.re - a.im*b.im, a.re*b.im + a.im*b.re };
}
__device__ __forceinline__ cf caddf(cf a, cf b) { return { a.re + b.re, a.im + b.im }; }
__device__ __forceinline__ cf cdivf(cf a, cf b) {
    float inv = 1.0f / (b.re*b.re + b.im*b.im);
    return { (a.re*b.re + a.im*b.im)*inv, (a.im*b.re - a.re*b.im)*inv };
}

// FINAL (R4 configuration, best median across repeated draws).
// Campaign summary:
//  - Fused single launch, t-major with register-carried u[t-1]: real win.
//  - Best kernel draw: 80.2us @ 6.18 TB/s (78% of 8TB/s spec); traffic at the
//    512 MB floor; ~6.2 TB/s is the repeatable 1:1 fp32 R/W stream ceiling.
//  - Measured run-to-run variance: +/-6us on identical SASS (R4 vs R13) —
//    all <=2us variant deltas (cache hints, t-split, launch_bounds) are noise.
//  - Real regressions to avoid: CHUNK=256 (regs 48, occ 53%), single-wave
//    persistent grid (lost block-level MLP, DRAM 69%).
//
// Phase 1 (threads 0..127): fp32 taps for this block's 128 channels -> smem.
//   dA = [[p0,-1],[-1,p1]] (off-diagonals exactly -1 from the reference's
//   elementwise division); 8 symmetric squarings => dA^256.
// Phase 2 (all 256 threads): t-major 2-tap causal conv,
//   out[b,t,d] = g0[d]*u[b,t,d] + g1[d]*u[b,t-1,d].
__global__ __launch_bounds__(256) void s4d_fused_kernel(
    const float* __restrict__ u,
    const float* __restrict__ A_real, const float* __restrict__ A_imag,
    const float* __restrict__ B_real, const float* __restrict__ B_imag,
    const float* __restrict__ C_real, const float* __restrict__ C_imag,
    const float* __restrict__ Dvec,
    float* __restrict__ out)
{
    __shared__ float s_g0[CHUNK];
    __shared__ float s_g1[CHUNK];

    const int tid    = threadIdx.x;
    const int chunk0 = blockIdx.x * CHUNK;

    if (tid < CHUNK) {
        const int d = chunk0 + tid;
        const float a0r = -expf(A_real[2*d]),   a0i = A_imag[2*d];
        const float a1r = -expf(A_real[2*d+1]), a1i = A_imag[2*d+1];

        cf p0 = cdivf({1.f + 0.5f*a0r,  0.5f*a0i},
                      {1.f - 0.5f*a0r, -0.5f*a0i});
        cf p1 = cdivf({1.f + 0.5f*a1r,  0.5f*a1i},
                      {1.f - 0.5f*a1r, -0.5f*a1i});

        cf m00 = p0, m01 = {-1.f, 0.f}, m11 = p1;
        #pragma unroll
        for (int s = 0; s < 8; s++) {           // M <- M^2 (symmetric), => M^256
            cf m01sq = cmulf(m01, m01);
            cf n00 = caddf(cmulf(m00, m00), m01sq);
            cf n01 = cmulf(m01, caddf(m00, m11));
            cf n11 = caddf(m01sq, cmulf(m11, m11));
            m00 = n00; m01 = n01; m11 = n11;
        }

        cf B0 = { B_real[2*d],   B_imag[2*d]   };
        cf B1 = { B_real[2*d+1], B_imag[2*d+1] };
        cf C0 = { C_real[2*d],   C_imag[2*d]   };
        cf C1 = { C_real[2*d+1], C_imag[2*d+1] };

        cf t0 = caddf(cmulf({1.f - m00.re, -m00.im}, B0),
                      cmulf({     -m01.re, -m01.im}, B1));
        cf t1 = caddf(cmulf({     -m01.re, -m01.im}, B0),
                      cmulf({1.f - m11.re, -m11.im}, B1));

        s_g0[tid] = (C0.re*t0.re - C0.im*t0.im) + Dvec[d];
        s_g1[tid] = (C1.re*t1.re - C1.im*t1.im);
    }
    __syncthreads();

    const int lane = tid & 31;          // float4 column within chunk
    const int w    = tid >> 5;          // t-group
    const int t0i  = w * 32;

    const float4 g0 = *reinterpret_cast<const float4*>(s_g0 + lane*4);
    const float4 g1 = *reinterpret_cast<const float4*>(s_g1 + lane*4);

    const unsigned int base =
        ((unsigned int)blockIdx.y * SEQ_L + (unsigned int)t0i) * D_MODEL
        + (unsigned int)chunk0 + (unsigned int)lane * 4u;

    const float4* __restrict__ up = reinterpret_cast<const float4*>(u + base);
    float4*       __restrict__ op = reinterpret_cast<float4*>(out + base);

    float4 uprev;
    if (t0i == 0) uprev = make_float4(0.f, 0.f, 0.f, 0.f);
    else          uprev = *reinterpret_cast<const float4*>(u + base - D_MODEL);

    #pragma unroll 8
    for (int k = 0; k < 32; k++) {
        float4 uv = up[(unsigned int)k * (D_MODEL/4)];
        float4 o;
        o.x = fmaf(g0.x, uv.x, g1.x * uprev.x);
        o.y = fmaf(g0.y, uv.y, g1.y * uprev.y);
        o.z = fmaf(g0.z, uv.z, g1.z * uprev.z);
        o.w = fmaf(g0.w, uv.w, g1.w * uprev.w);
        op[(unsigned int)k * (D_MODEL/4)] = o;
        uprev = uv;
    }
}

extern "C" void kernel_launch(void* const* d_in, const int* in_sizes, int n_in,
                              void* d_out, int out_size) {
    const float* u      = (const float*)d_in[0];
    const float* A_real = (const float*)d_in[1];
    const float* A_imag = (const float*)d_in[2];
    const float* B_real = (const float*)d_in[3];
    const float* B_imag = (const float*)d_in[4];
    const float* C_real = (const float*)d_in[5];
    const float* C_imag = (const float*)d_in[6];
    const float* Dvec   = (const float*)d_in[7];
    float* out = (float*)d_out;

    dim3 grid(D_MODEL / CHUNK, BATCH_N);   // (16, 128) = 2048 blocks
    s4d_fused_kernel<<<grid, 256>>>(u, A_real, A_imag, B_real, B_imag,
                                    C_real, C_imag, Dvec, out);
}